// round 8
// baseline (speedup 1.0000x reference)
#include <cuda_runtime.h>
#include <cuda_bf16.h>
#include <cstdint>

#define NN  100000
#define NE  1600000
#define NE2 1700000   // NE + NN self loops
#define HC  256       // heads*channels for layers 0,1
#define F2  40        // output cols layer 2

// ---------------- scratch (static device globals; no runtime allocation) ----
__device__ float g_X[(size_t)NN * HC];     // transformed features of current layer
__device__ float g_H[(size_t)NN * HC];     // hidden activations between layers
__device__ float g_ALS[(size_t)NN * 8];    // per-node attention logits (src side)
__device__ float g_ALD[(size_t)NN * 8];    // per-node attention logits (dst side)
__device__ int   g_deg[NN];
__device__ int   g_rowptr[NN + 1];
__device__ int   g_cursor[NN];
__device__ int   g_colsrc[NE2];
__device__ int   g_is64;                   // 1 if edge_index is int64, 0 if int32

// ---------------- edge dtype detection -------------------------------------
__global__ void k_detect(const unsigned int* __restrict__ ew) {
    // If the buffer is int64 little-endian with values in [0, NN), every
    // odd 32-bit word (the high half) of the first 32 elements is zero.
    // If it is int32, odd words are edge values (~all nonzero).
    if (threadIdx.x == 0 && blockIdx.x == 0) {
        int is64 = 1;
        for (int i = 0; i < 32; i++) {
            if (ew[2 * i + 1] != 0u) { is64 = 0; break; }
        }
        g_is64 = is64;
    }
}

__device__ __forceinline__ int edge_at(const void* ei, size_t idx, int is64) {
    if (is64) return (int)((const long long*)ei)[idx];
    return ((const int*)ei)[idx];
}

// ---------------- CSR build ------------------------------------------------
__global__ void k_zero_deg() {
    int i = blockIdx.x * blockDim.x + threadIdx.x;
    if (i < NN) g_deg[i] = 0;
}

__global__ void k_deg(const void* __restrict__ ei) {
    int e = blockIdx.x * blockDim.x + threadIdx.x;
    if (e >= NE2) return;
    int is64 = g_is64;
    int dst = (e < NE) ? edge_at(ei, (size_t)NE + e, is64) : (e - NE);
    if ((unsigned)dst >= NN) return;   // defensive
    atomicAdd(&g_deg[dst], 1);
}

// single-block exclusive scan over 100000 degrees; also writes cursor
__global__ void k_scan() {
    __shared__ int sums[1024];
    const int tid = threadIdx.x;
    const int CH = (NN + 1023) / 1024;        // 98
    int start = tid * CH;
    int end = start + CH; if (end > NN) end = NN;
    if (start > NN) start = NN;
    int s = 0;
    for (int i = start; i < end; i++) s += g_deg[i];
    sums[tid] = s;
    __syncthreads();
    for (int off = 1; off < 1024; off <<= 1) {
        int v = (tid >= off) ? sums[tid - off] : 0;
        __syncthreads();
        sums[tid] += v;
        __syncthreads();
    }
    int run = (tid == 0) ? 0 : sums[tid - 1];
    for (int i = start; i < end; i++) {
        g_rowptr[i] = run;
        g_cursor[i] = run;
        run += g_deg[i];
    }
    if (tid == 0) g_rowptr[NN] = sums[1023];
}

__global__ void k_fill(const void* __restrict__ ei) {
    int e = blockIdx.x * blockDim.x + threadIdx.x;
    if (e >= NE2) return;
    int is64 = g_is64;
    int src, dst;
    if (e < NE) {
        src = edge_at(ei, (size_t)e, is64);
        dst = edge_at(ei, (size_t)NE + e, is64);
    } else {
        src = dst = e - NE;
    }
    if ((unsigned)dst >= NN || (unsigned)src >= NN) return;  // defensive
    int pos = atomicAdd(&g_cursor[dst], 1);
    g_colsrc[pos] = src;
}

// ---------------- SGEMM ----------------------------------------------------
template<int BM, int BN, int BK, int TM, int TN>
__global__ void k_sgemm(const float* __restrict__ A, const float* __restrict__ B,
                        float* __restrict__ C, int M, int N, int K) {
    __shared__ float As[BK][BM];
    __shared__ float Bs[BK][BN];
    constexpr int TX = BN / TN;
    constexpr int TY = BM / TM;
    const int tid = threadIdx.x;       // TX*TY = 256 threads
    const int tx = tid % TX;
    const int ty = tid / TX;
    const int row0 = blockIdx.y * BM;
    const int col0 = blockIdx.x * BN;

    float acc[TM][TN];
#pragma unroll
    for (int i = 0; i < TM; i++)
#pragma unroll
        for (int j = 0; j < TN; j++) acc[i][j] = 0.f;

    for (int k0 = 0; k0 < K; k0 += BK) {
        for (int idx = tid; idx < BM * BK; idx += TX * TY) {
            int r = idx / BK, kk = idx % BK;
            int gr = row0 + r;
            As[kk][r] = (gr < M) ? A[(size_t)gr * K + k0 + kk] : 0.f;
        }
        for (int idx = tid; idx < BK * BN; idx += TX * TY) {
            int kk = idx / BN, c = idx % BN;
            int gc = col0 + c;
            Bs[kk][c] = (gc < N) ? B[(size_t)(k0 + kk) * N + gc] : 0.f;
        }
        __syncthreads();
#pragma unroll
        for (int kk = 0; kk < BK; kk++) {
            float rm[TM], rn[TN];
#pragma unroll
            for (int i = 0; i < TM; i++) rm[i] = As[kk][ty * TM + i];
#pragma unroll
            for (int j = 0; j < TN; j++) rn[j] = Bs[kk][tx * TN + j];
#pragma unroll
            for (int i = 0; i < TM; i++)
#pragma unroll
                for (int j = 0; j < TN; j++) acc[i][j] += rm[i] * rn[j];
        }
        __syncthreads();
    }
#pragma unroll
    for (int i = 0; i < TM; i++) {
        int gr = row0 + ty * TM + i;
        if (gr >= M) continue;
#pragma unroll
        for (int j = 0; j < TN; j++) {
            int gc = col0 + tx * TN + j;
            if (gc < N) C[(size_t)gr * N + gc] = acc[i][j];
        }
    }
}

// ---------------- attention logits (al_src / al_dst) -----------------------
// layers 0,1: x row is [8 heads][32 ch]; lane l owns cols [8l,8l+8) -> head l>>2
__global__ void k_al8(const float* __restrict__ X,
                      const float* __restrict__ asrc, const float* __restrict__ adst) {
    int gt = blockIdx.x * blockDim.x + threadIdx.x;
    int v = gt >> 5;
    if (v >= NN) return;
    int l = gt & 31;
    int h = l >> 2;
    int cb = (l & 3) * 8;
    const float* xr = X + (size_t)v * HC + l * 8;
    const float* as = asrc + h * 32 + cb;
    const float* ad = adst + h * 32 + cb;
    float ps = 0.f, pd = 0.f;
#pragma unroll
    for (int j = 0; j < 8; j++) {
        float x = xr[j];
        ps += x * as[j];
        pd += x * ad[j];
    }
    ps += __shfl_xor_sync(0xffffffffu, ps, 1);
    ps += __shfl_xor_sync(0xffffffffu, ps, 2);
    pd += __shfl_xor_sync(0xffffffffu, pd, 1);
    pd += __shfl_xor_sync(0xffffffffu, pd, 2);
    if ((l & 3) == 0) {
        g_ALS[(size_t)v * 8 + h] = ps;
        g_ALD[(size_t)v * 8 + h] = pd;
    }
}

// layer 2: H=1, C=40; lane l covers col l (and 32+l if l<8)
__global__ void k_al1(const float* __restrict__ X,
                      const float* __restrict__ asrc, const float* __restrict__ adst) {
    int gt = blockIdx.x * blockDim.x + threadIdx.x;
    int v = gt >> 5;
    if (v >= NN) return;
    int l = gt & 31;
    const float* xr = X + (size_t)v * F2;
    float ps = 0.f, pd = 0.f;
    if (l < F2) { ps = xr[l] * asrc[l]; pd = xr[l] * adst[l]; }
    if (l < 8) {
        ps += xr[32 + l] * asrc[32 + l];
        pd += xr[32 + l] * adst[32 + l];
    }
#pragma unroll
    for (int off = 16; off >= 1; off >>= 1) {
        ps += __shfl_xor_sync(0xffffffffu, ps, off);
        pd += __shfl_xor_sync(0xffffffffu, pd, off);
    }
    if (l == 0) { g_ALS[v] = ps; g_ALD[v] = pd; }
}

// ---------------- aggregation (softmax + weighted gather), layers 0,1 ------
__global__ void k_agg8(const float* __restrict__ X, const float* __restrict__ bias,
                       float* __restrict__ out, int do_elu) {
    int gt = blockIdx.x * blockDim.x + threadIdx.x;
    int v = gt >> 5;
    if (v >= NN) return;
    int l = gt & 31;
    int h = l >> 2;
    int beg = g_rowptr[v];
    int end = g_rowptr[v + 1];
    float ald = g_ALD[(size_t)v * 8 + h];

    // pass A: per-head max (replicated across the 4 lanes of each head)
    float m = -3.4e38f;
    for (int e = beg; e < end; e++) {
        int s = g_colsrc[e];
        float t = g_ALS[(size_t)s * 8 + h] + ald;
        t = t > 0.f ? t : 0.2f * t;
        m = fmaxf(m, t);
    }

    // pass B: sum of exp + weighted feature accumulation
    float sum = 0.f;
    float4 a0 = make_float4(0.f, 0.f, 0.f, 0.f);
    float4 a1 = make_float4(0.f, 0.f, 0.f, 0.f);
    for (int e = beg; e < end; e++) {
        int s = g_colsrc[e];
        float t = g_ALS[(size_t)s * 8 + h] + ald;
        t = t > 0.f ? t : 0.2f * t;
        float w = __expf(t - m);
        sum += w;
        const float4* xr = (const float4*)(X + (size_t)s * HC + l * 8);
        float4 x0 = xr[0];
        float4 x1 = xr[1];
        a0.x += w * x0.x; a0.y += w * x0.y; a0.z += w * x0.z; a0.w += w * x0.w;
        a1.x += w * x1.x; a1.y += w * x1.y; a1.z += w * x1.z; a1.w += w * x1.w;
    }
    float inv = (sum > 0.f) ? 1.f / sum : 0.f;
    const float* bb = bias + l * 8;
    float o[8];
    o[0] = a0.x * inv + bb[0]; o[1] = a0.y * inv + bb[1];
    o[2] = a0.z * inv + bb[2]; o[3] = a0.w * inv + bb[3];
    o[4] = a1.x * inv + bb[4]; o[5] = a1.y * inv + bb[5];
    o[6] = a1.z * inv + bb[6]; o[7] = a1.w * inv + bb[7];
    if (do_elu) {
#pragma unroll
        for (int j = 0; j < 8; j++)
            o[j] = o[j] > 0.f ? o[j] : (__expf(o[j]) - 1.f);
    }
    float4* orow = (float4*)(out + (size_t)v * HC + l * 8);
    orow[0] = make_float4(o[0], o[1], o[2], o[3]);
    orow[1] = make_float4(o[4], o[5], o[6], o[7]);
}

// ---------------- aggregation layer 2 (H=1, C=40) --------------------------
__global__ void k_agg1(const float* __restrict__ X, const float* __restrict__ bias,
                       float* __restrict__ out) {
    int gt = blockIdx.x * blockDim.x + threadIdx.x;
    int v = gt >> 5;
    if (v >= NN) return;
    int l = gt & 31;
    int beg = g_rowptr[v];
    int end = g_rowptr[v + 1];
    float ald = g_ALD[v];

    float m = -3.4e38f;
    for (int e = beg; e < end; e++) {
        int s = g_colsrc[e];
        float t = g_ALS[s] + ald;
        t = t > 0.f ? t : 0.2f * t;
        m = fmaxf(m, t);
    }
    float sum = 0.f, acc0 = 0.f, acc1 = 0.f;
    for (int e = beg; e < end; e++) {
        int s = g_colsrc[e];
        float t = g_ALS[s] + ald;
        t = t > 0.f ? t : 0.2f * t;
        float w = __expf(t - m);
        sum += w;
        const float* xr = X + (size_t)s * F2;
        if (l < F2) acc0 += w * xr[l];
        if (l < 8)  acc1 += w * xr[32 + l];
    }
    float inv = (sum > 0.f) ? 1.f / sum : 0.f;
    if (l < F2) out[(size_t)v * F2 + l] = acc0 * inv + bias[l];
    if (l < 8)  out[(size_t)v * F2 + 32 + l] = acc1 * inv + bias[32 + l];
}

// ---------------- launch ----------------------------------------------------
extern "C" void kernel_launch(void* const* d_in, const int* in_sizes, int n_in,
                              void* d_out, int out_size) {
    const float* feats = (const float*)d_in[0];
    const void*  ei    = d_in[1];
    const float* W0  = (const float*)d_in[2];
    const float* as0 = (const float*)d_in[3];
    const float* ad0 = (const float*)d_in[4];
    const float* b0  = (const float*)d_in[5];
    const float* W1  = (const float*)d_in[6];
    const float* as1 = (const float*)d_in[7];
    const float* ad1 = (const float*)d_in[8];
    const float* b1  = (const float*)d_in[9];
    const float* W2  = (const float*)d_in[10];
    const float* as2 = (const float*)d_in[11];
    const float* ad2 = (const float*)d_in[12];
    const float* b2  = (const float*)d_in[13];
    float* out = (float*)d_out;

    void *pXv, *pHv;
    cudaGetSymbolAddress(&pXv, g_X);
    cudaGetSymbolAddress(&pHv, g_H);
    float* pX = (float*)pXv;
    float* pH = (float*)pHv;

    const int EB = (NE2 + 255) / 256;
    const int WB = (NN * 32 + 255) / 256;   // one warp per node
    const dim3 g256(2, (NN + 127) / 128);
    const dim3 g40(1, (NN + 127) / 128);

    // CSR build (runs inside the graph each replay)
    k_detect<<<1, 32>>>((const unsigned int*)ei);
    k_zero_deg<<<(NN + 255) / 256, 256>>>();
    k_deg<<<EB, 256>>>(ei);
    k_scan<<<1, 1024>>>();
    k_fill<<<EB, 256>>>(ei);

    // ---- layer 0 ----
    k_sgemm<128, 128, 8, 8, 8><<<g256, 256>>>(feats, W0, pX, NN, HC, 128);
    k_al8<<<WB, 256>>>(pX, as0, ad0);
    k_agg8<<<WB, 256>>>(pX, b0, pH, 1);

    // ---- layer 1 ----
    k_sgemm<128, 128, 8, 8, 8><<<g256, 256>>>(pH, W1, pX, NN, HC, HC);
    k_al8<<<WB, 256>>>(pX, as1, ad1);
    k_agg8<<<WB, 256>>>(pX, b1, pH, 1);

    // ---- layer 2 ----
    k_sgemm<128, 64, 8, 8, 4><<<g40, 256>>>(pH, W2, pX, NN, F2, HC);
    k_al1<<<WB, 256>>>(pX, as2, ad2);
    k_agg1<<<WB, 256>>>(pX, b2, out);
}